// round 1
// baseline (speedup 1.0000x reference)
#include <cuda_runtime.h>
#include <cstddef>

#define FEAT 256
#define EMB  256
#define BATCHN 10000
#define NSAMP 32
#define TB 16
#define NTHREADS 256

// Scratch for precomputed M = Wq @ Wk^T  and  d = Wk @ bq
__device__ float g_M[FEAT * FEAT];
__device__ float g_d[FEAT];

// ---------------------------------------------------------------------------
// Kernel 1a: M[g,f] = sum_e Wq[g,e] * Wk[f,e]    (64x64 tile per block)
// ---------------------------------------------------------------------------
__global__ __launch_bounds__(256) void precompute_M_kernel(
    const float* __restrict__ Wq, const float* __restrict__ Wk)
{
    __shared__ float sA[64][16];   // Wq rows  (g-major, e chunk)
    __shared__ float sB[64][16];   // Wk rows  (f-major, e chunk)
    const int tx = threadIdx.x & 15;        // f micro index
    const int ty = threadIdx.x >> 4;        // g micro index
    const int g0 = blockIdx.x * 64;
    const int f0 = blockIdx.y * 64;

    float acc[4][4] = {};
    for (int k0 = 0; k0 < EMB; k0 += 16) {
        // 64x16 tiles, contiguous in e -> coalesced
        for (int i = threadIdx.x; i < 64 * 16; i += 256) {
            int r = i >> 4, c = i & 15;
            sA[r][c] = Wq[(g0 + r) * EMB + k0 + c];
            sB[r][c] = Wk[(f0 + r) * EMB + k0 + c];
        }
        __syncthreads();
        #pragma unroll
        for (int kk = 0; kk < 16; kk++) {
            float a[4], b[4];
            #pragma unroll
            for (int i = 0; i < 4; i++) a[i] = sA[ty * 4 + i][kk];
            #pragma unroll
            for (int j = 0; j < 4; j++) b[j] = sB[tx * 4 + j][kk];
            #pragma unroll
            for (int i = 0; i < 4; i++)
                #pragma unroll
                for (int j = 0; j < 4; j++)
                    acc[i][j] += a[i] * b[j];
        }
        __syncthreads();
    }
    #pragma unroll
    for (int i = 0; i < 4; i++)
        #pragma unroll
        for (int j = 0; j < 4; j++)
            g_M[(g0 + ty * 4 + i) * FEAT + (f0 + tx * 4 + j)] = acc[i][j];
}

// ---------------------------------------------------------------------------
// Kernel 1b: d[f] = sum_e Wk[f,e] * bq[e]   (one warp per f)
// ---------------------------------------------------------------------------
__global__ __launch_bounds__(256) void precompute_d_kernel(
    const float* __restrict__ Wk, const float* __restrict__ bq)
{
    int gwarp = (blockIdx.x * blockDim.x + threadIdx.x) >> 5;
    int lane = threadIdx.x & 31;
    if (gwarp < FEAT) {
        float s = 0.f;
        #pragma unroll
        for (int k = lane; k < EMB; k += 32)
            s += Wk[gwarp * EMB + k] * bq[k];
        #pragma unroll
        for (int o = 16; o; o >>= 1) s += __shfl_xor_sync(0xFFFFFFFFu, s, o);
        if (lane == 0) g_d[gwarp] = s;
    }
}

// ---------------------------------------------------------------------------
// Kernel 2: per-block = TB batches
//   u = x_self @ M + d ; scores_s = u . x_s ; softmax ; z = sum attn * x_s ;
//   out = z @ Wv + bv
// ---------------------------------------------------------------------------
__global__ __launch_bounds__(NTHREADS) void attn_main_kernel(
    const int*   __restrict__ nodes,
    const int*   __restrict__ neigh,
    const float* __restrict__ feat,
    const float* __restrict__ Wv,
    const float* __restrict__ bv,
    float*       __restrict__ out)
{
    extern __shared__ float smem[];
    float* sx  = smem;                       // [TB][FEAT]  self feats
    float* su  = sx + TB * FEAT;             // [TB][FEAT]  u, later z
    float* snb = su + TB * FEAT;             // [NSAMP][FEAT] neighbor feats
    float* ssc = snb + NSAMP * FEAT;         // [NSAMP] scores / attn

    const int tid  = threadIdx.x;
    const int lane = tid & 31;
    const int warp = tid >> 5;
    const int b0   = blockIdx.x * TB;

    // ---- load TB self feature rows (float4 coalesced) ----
    for (int i = tid; i < TB * (FEAT / 4); i += NTHREADS) {
        int t = i / (FEAT / 4), c = i % (FEAT / 4);
        int node = nodes[b0 + t];
        ((float4*)(sx + t * FEAT))[c] =
            ((const float4*)(feat + (size_t)node * FEAT))[c];
    }
    __syncthreads();

    // ---- u[t][f] = sum_g sx[t][g] * M[g][f] + d[f] ;  f = tid ----
    {
        float acc[TB];
        #pragma unroll
        for (int t = 0; t < TB; t++) acc[t] = 0.f;
        #pragma unroll 4
        for (int g = 0; g < FEAT; g++) {
            float m = g_M[g * FEAT + tid];
            #pragma unroll
            for (int t = 0; t < TB; t++) acc[t] += sx[t * FEAT + g] * m;
        }
        float dv = g_d[tid];
        #pragma unroll
        for (int t = 0; t < TB; t++) su[t * FEAT + tid] = acc[t] + dv;
    }
    __syncthreads();

    // ---- per-batch: gather neighbors, scores, softmax, z (overwrites u) ----
    for (int t = 0; t < TB; t++) {
        for (int i = tid; i < NSAMP * (FEAT / 4); i += NTHREADS) {
            int s = i / (FEAT / 4), c = i % (FEAT / 4);
            int nb = neigh[(size_t)(b0 + t) * NSAMP + s];
            ((float4*)(snb + s * FEAT))[c] =
                ((const float4*)(feat + (size_t)nb * FEAT))[c];
        }
        __syncthreads();

        // scores: 8 warps x 4 neighbors each, 256-dot via lanes
        #pragma unroll
        for (int si = 0; si < NSAMP / 8; si++) {
            int s = warp + si * 8;
            float dot = 0.f;
            #pragma unroll
            for (int k = 0; k < FEAT / 32; k++)
                dot += snb[s * FEAT + lane + 32 * k] * su[t * FEAT + lane + 32 * k];
            #pragma unroll
            for (int o = 16; o; o >>= 1) dot += __shfl_xor_sync(0xFFFFFFFFu, dot, o);
            if (lane == 0) ssc[s] = dot;
        }
        __syncthreads();

        // softmax over 32 scores (warp 0)
        if (warp == 0) {
            float v = ssc[lane];
            float mx = v;
            #pragma unroll
            for (int o = 16; o; o >>= 1) mx = fmaxf(mx, __shfl_xor_sync(0xFFFFFFFFu, mx, o));
            float e = expf(v - mx);
            float sm = e;
            #pragma unroll
            for (int o = 16; o; o >>= 1) sm += __shfl_xor_sync(0xFFFFFFFFu, sm, o);
            ssc[lane] = e / sm;
        }
        __syncthreads();

        // z[f] = sum_s attn[s] * snb[s][f]  -> overwrite su[t]
        float z = 0.f;
        #pragma unroll
        for (int s = 0; s < NSAMP; s++)
            z += ssc[s] * snb[s * FEAT + tid];
        su[t * FEAT + tid] = z;
        __syncthreads();   // protect snb/ssc before next iteration
    }

    // ---- out[t][e] = sum_f z[t][f] * Wv[f][e] + bv[e] ;  e = tid ----
    {
        float acc[TB];
        float b = bv[tid];
        #pragma unroll
        for (int t = 0; t < TB; t++) acc[t] = b;
        #pragma unroll 4
        for (int g = 0; g < FEAT; g++) {
            float w = Wv[g * EMB + tid];
            #pragma unroll
            for (int t = 0; t < TB; t++) acc[t] += su[t * FEAT + g] * w;
        }
        #pragma unroll
        for (int t = 0; t < TB; t++)
            out[(size_t)(b0 + t) * EMB + tid] = acc[t];
    }
}

// ---------------------------------------------------------------------------
// Launch
// ---------------------------------------------------------------------------
extern "C" void kernel_launch(void* const* d_in, const int* in_sizes, int n_in,
                              void* d_out, int out_size)
{
    // Input order (metadata): nodes, neigh_idx, id2feat, Wq, bq, Wk, bk, Wv, bv
    const int*   nodes = (const int*)  d_in[0];
    const int*   neigh = (const int*)  d_in[1];
    const float* feat  = (const float*)d_in[2];
    const float* Wq    = (const float*)d_in[3];
    const float* bq    = (const float*)d_in[4];
    const float* Wk    = (const float*)d_in[5];
    // bk (d_in[6]) is provably softmax-invariant: score_s = Q.K_s = Q.(x_s Wk) + Q.bk,
    // and Q.bk is constant over s -> drops out of softmax. Unused.
    const float* Wv    = (const float*)d_in[7];
    const float* bv    = (const float*)d_in[8];
    float* out = (float*)d_out;

    const size_t smem_bytes = (size_t)(2 * TB * FEAT + NSAMP * FEAT + NSAMP) * sizeof(float);
    cudaFuncSetAttribute(attn_main_kernel,
                         cudaFuncAttributeMaxDynamicSharedMemorySize,
                         (int)smem_bytes);

    dim3 gridM(FEAT / 64, FEAT / 64);
    precompute_M_kernel<<<gridM, 256>>>(Wq, Wk);
    precompute_d_kernel<<<(FEAT * 32 + 255) / 256, 256>>>(Wk, bq);

    const int nblocks = (BATCHN + TB - 1) / TB;   // 625
    attn_main_kernel<<<nblocks, NTHREADS, smem_bytes>>>(
        nodes, neigh, feat, Wv, bv, out);
}

// round 3
// speedup vs baseline: 2.2624x; 2.2624x over previous
#include <cuda_runtime.h>
#include <cuda_bf16.h>
#include <cstdint>
#include <cstddef>

#define FEAT 256
#define EMB  256
#define BATCHN 10000
#define NSAMP 32

// ---------------------------------------------------------------------------
// Device-global scratch (no allocs allowed)
// ---------------------------------------------------------------------------
__device__ float g_d[FEAT];                       // d = Wk @ bq
__device__ float g_U[BATCHN * FEAT];              // u per batch
__device__ float g_Z[BATCHN * FEAT];              // attn-weighted feats
__device__ __nv_bfloat16 g_Mh[FEAT * FEAT];       // [f][g] = hi(M[g][f]),  M = Wq Wk^T
__device__ __nv_bfloat16 g_Ml[FEAT * FEAT];       // [f][g] = lo(M[g][f])
__device__ __nv_bfloat16 g_Wvh[EMB * FEAT];       // [e][f] = hi(Wv[f][e])
__device__ __nv_bfloat16 g_Wvl[EMB * FEAT];       // [e][f] = lo(Wv[f][e])

// ---------------------------------------------------------------------------
// Kernel 1a: M = Wq @ Wk^T, written transposed as bf16 hi/lo.
// grid (16,16): each block a 16x16 tile; thread = one output element.
// ---------------------------------------------------------------------------
__global__ __launch_bounds__(256) void precompute_M_kernel(
    const float* __restrict__ Wq, const float* __restrict__ Wk)
{
    __shared__ float sQ[16][260];
    __shared__ float sK[16][260];
    const int g0 = blockIdx.x * 16, f0 = blockIdx.y * 16;
    const int tid = threadIdx.x;
    for (int i = tid; i < 16 * 64; i += 256) {         // 16 rows x 64 float4
        int r = i >> 6, v = i & 63;
        float4 q = ((const float4*)(Wq + (g0 + r) * EMB))[v];
        float4 k = ((const float4*)(Wk + (f0 + r) * EMB))[v];
        sQ[r][v * 4 + 0] = q.x; sQ[r][v * 4 + 1] = q.y; sQ[r][v * 4 + 2] = q.z; sQ[r][v * 4 + 3] = q.w;
        sK[r][v * 4 + 0] = k.x; sK[r][v * 4 + 1] = k.y; sK[r][v * 4 + 2] = k.z; sK[r][v * 4 + 3] = k.w;
    }
    __syncthreads();
    const int fx = tid & 15, gy = tid >> 4;
    float a0 = 0.f, a1 = 0.f, a2 = 0.f, a3 = 0.f;
    #pragma unroll 8
    for (int e = 0; e < EMB; e += 4) {
        a0 += sQ[gy][e + 0] * sK[fx][e + 0];
        a1 += sQ[gy][e + 1] * sK[fx][e + 1];
        a2 += sQ[gy][e + 2] * sK[fx][e + 2];
        a3 += sQ[gy][e + 3] * sK[fx][e + 3];
    }
    float m = (a0 + a1) + (a2 + a3);
    __nv_bfloat16 h = __float2bfloat16(m);
    float lo = m - __bfloat162float(h);
    int o = (f0 + fx) * FEAT + (g0 + gy);
    g_Mh[o] = h;
    g_Ml[o] = __float2bfloat16(lo);
}

// ---------------------------------------------------------------------------
// Kernel 1b: d[f] = Wk[f,:] . bq   (one warp per f)
// ---------------------------------------------------------------------------
__global__ __launch_bounds__(256) void precompute_d_kernel(
    const float* __restrict__ Wk, const float* __restrict__ bq)
{
    int f = (blockIdx.x * blockDim.x + threadIdx.x) >> 5;
    int lane = threadIdx.x & 31;
    if (f < FEAT) {
        float s = 0.f;
        #pragma unroll
        for (int k = lane; k < EMB; k += 32) s += Wk[f * EMB + k] * bq[k];
        #pragma unroll
        for (int o = 16; o; o >>= 1) s += __shfl_xor_sync(0xFFFFFFFFu, s, o);
        if (lane == 0) g_d[f] = s;
    }
}

// ---------------------------------------------------------------------------
// Kernel 1c: Wv -> transposed bf16 hi/lo
// ---------------------------------------------------------------------------
__global__ __launch_bounds__(256) void prep_wv_kernel(const float* __restrict__ Wv)
{
    int f = blockIdx.x, e = threadIdx.x;
    float v = Wv[f * EMB + e];
    __nv_bfloat16 h = __float2bfloat16(v);
    float lo = v - __bfloat162float(h);
    g_Wvh[e * FEAT + f] = h;
    g_Wvl[e * FEAT + f] = __float2bfloat16(lo);
}

// ---------------------------------------------------------------------------
// bf16 split-precision MMA GEMM: C[m][n] = sum_k A[m][k]*Bt[n][k] + bias[n]
// BM=BN=128, K chunked by 64. mma.sync.m16n8k16 (base sm_100-safe).
// Block: 256 threads = 8 warps, warp grid 2(m) x 4(n), warp tile 64x32.
// ---------------------------------------------------------------------------
#define SA 72                    // smem row stride in bf16 (64 + 8 pad)
#define TILE_B (128 * SA * 2)    // 18432 bytes per tile
#define SM_BIAS 0
#define SM_IDX  512
#define SM_AH   1024
#define SM_AL   (SM_AH + TILE_B)
#define SM_BH   (SM_AL + TILE_B)
#define SM_BL   (SM_BH + TILE_B)
#define SMEM_GEMM (SM_BL + TILE_B)

__device__ __forceinline__ void mma_bf16(float* c, const uint32_t* a, const uint32_t* b)
{
    asm volatile(
        "mma.sync.aligned.m16n8k16.row.col.f32.bf16.bf16.f32 "
        "{%0,%1,%2,%3}, {%4,%5,%6,%7}, {%8,%9}, {%0,%1,%2,%3};\n"
        : "+f"(c[0]), "+f"(c[1]), "+f"(c[2]), "+f"(c[3])
        : "r"(a[0]), "r"(a[1]), "r"(a[2]), "r"(a[3]), "r"(b[0]), "r"(b[1]));
}

__device__ __forceinline__ void gemm_body(
    const float* __restrict__ A, const int* __restrict__ gidx, int Mrows,
    const __nv_bfloat16* __restrict__ Bh, const __nv_bfloat16* __restrict__ Bl,
    const float* __restrict__ bias, float* __restrict__ C)
{
    extern __shared__ char smem[];
    float* sBias = (float*)(smem + SM_BIAS);
    int*   sIdx  = (int*)(smem + SM_IDX);
    __nv_bfloat16* sAh = (__nv_bfloat16*)(smem + SM_AH);
    __nv_bfloat16* sAl = (__nv_bfloat16*)(smem + SM_AL);
    __nv_bfloat16* sBhS = (__nv_bfloat16*)(smem + SM_BH);
    __nv_bfloat16* sBlS = (__nv_bfloat16*)(smem + SM_BL);

    const int tid = threadIdx.x, wid = tid >> 5, lane = tid & 31;
    const int gid = lane >> 2, tg = lane & 3;           // mma fragment coords
    const int m0 = blockIdx.x * 128, n0 = blockIdx.y * 128;
    const int wm = (wid >> 2) * 64;                     // warp m offset in tile
    const int wn = (wid & 3) * 32;                      // warp n offset in tile

    if (tid < 128) {
        sBias[tid] = bias[n0 + tid];
        int m = m0 + tid; if (m >= Mrows) m = Mrows - 1;
        sIdx[tid] = gidx ? gidx[m] : m;
    }
    __syncthreads();

    float c[4][4][4];                                   // [mi][ni][frag]
    #pragma unroll
    for (int mi = 0; mi < 4; mi++)
        #pragma unroll
        for (int ni = 0; ni < 4; ni++)
            #pragma unroll
            for (int q = 0; q < 4; q++) c[mi][ni][q] = 0.f;

    for (int ch = 0; ch < 4; ch++) {
        // ---- stage A chunk: 128 rows x 64 floats -> bf16 hi/lo ----
        #pragma unroll
        for (int it = 0; it < 8; it++) {
            int i = tid + it * 256;                     // 2048 float4
            int r = i >> 4, v = i & 15;
            float4 f = ((const float4*)(A + (size_t)sIdx[r] * FEAT + ch * 64))[v];
            __nv_bfloat162 h01 = __floats2bfloat162_rn(f.x, f.y);
            __nv_bfloat162 h23 = __floats2bfloat162_rn(f.z, f.w);
            __nv_bfloat162 l01 = __floats2bfloat162_rn(f.x - __bfloat162float(h01.x),
                                                       f.y - __bfloat162float(h01.y));
            __nv_bfloat162 l23 = __floats2bfloat162_rn(f.z - __bfloat162float(h23.x),
                                                       f.w - __bfloat162float(h23.y));
            *(uint2*)(sAh + r * SA + v * 4) = make_uint2(*(uint32_t*)&h01, *(uint32_t*)&h23);
            *(uint2*)(sAl + r * SA + v * 4) = make_uint2(*(uint32_t*)&l01, *(uint32_t*)&l23);
        }
        // ---- stage B chunk: 128 rows x 64 bf16 (hi and lo), straight copy ----
        #pragma unroll
        for (int it = 0; it < 4; it++) {
            int i = tid + it * 256;                     // 1024 uint4
            int r = i >> 3, v = i & 7;
            *(uint4*)(sBhS + r * SA + v * 8) = ((const uint4*)(Bh + (size_t)(n0 + r) * FEAT + ch * 64))[v];
            *(uint4*)(sBlS + r * SA + v * 8) = ((const uint4*)(Bl + (size_t)(n0 + r) * FEAT + ch * 64))[v];
        }
        __syncthreads();

        // ---- compute: 4 k16 steps, 3 split passes fused ----
        #pragma unroll
        for (int k16 = 0; k16 < 4; k16++) {
            const int ko = k16 * 16 + tg * 2;
            uint32_t ah[4][4], al[4][4], bh[4][2], bl[4][2];
            #pragma unroll
            for (int mi = 0; mi < 4; mi++) {
                const __nv_bfloat16* pr0 = sAh + (wm + mi * 16 + gid) * SA + ko;
                const __nv_bfloat16* pr8 = pr0 + 8 * SA;
                ah[mi][0] = *(const uint32_t*)pr0;
                ah[mi][1] = *(const uint32_t*)pr8;
                ah[mi][2] = *(const uint32_t*)(pr0 + 8);
                ah[mi][3] = *(const uint32_t*)(pr8 + 8);
                const __nv_bfloat16* qr0 = sAl + (wm + mi * 16 + gid) * SA + ko;
                const __nv_bfloat16* qr8 = qr0 + 8 * SA;
                al[mi][0] = *(const uint32_t*)qr0;
                al[mi][1] = *(const uint32_t*)qr8;
                al[mi][2] = *(const uint32_t*)(qr0 + 8);
                al[mi][3] = *(const uint32_t*)(qr8 + 8);
            }
            #pragma unroll
            for (int ni = 0; ni < 4; ni++) {
                const __nv_bfloat16* pb = sBhS + (wn + ni * 8 + gid) * SA + ko;
                bh[ni][0] = *(const uint32_t*)pb;
                bh[ni][1] = *(const uint32_t*)(pb + 8);
                const __nv_bfloat16* qb = sBlS + (wn + ni * 8 + gid) * SA + ko;
                bl[ni][0] = *(const uint32_t*)qb;
                bl[ni][1] = *(const uint32_t*)(qb + 8);
            }
            #pragma unroll
            for (int mi = 0; mi < 4; mi++)
                #pragma unroll
                for (int ni = 0; ni < 4; ni++) {
                    mma_bf16(c[mi][ni], ah[mi], bh[ni]);
                    mma_bf16(c[mi][ni], ah[mi], bl[ni]);
                    mma_bf16(c[mi][ni], al[mi], bh[ni]);
                }
        }
        __syncthreads();
    }

    // ---- epilogue: bias + store ----
    #pragma unroll
    for (int mi = 0; mi < 4; mi++) {
        int r0 = m0 + wm + mi * 16 + gid;
        #pragma unroll
        for (int ni = 0; ni < 4; ni++) {
            int col = wn + ni * 8 + tg * 2;
            float b0 = sBias[col], b1 = sBias[col + 1];
            if (r0 < Mrows)
                *(float2*)(C + (size_t)r0 * EMB + n0 + col) =
                    make_float2(c[mi][ni][0] + b0, c[mi][ni][1] + b1);
            if (r0 + 8 < Mrows)
                *(float2*)(C + (size_t)(r0 + 8) * EMB + n0 + col) =
                    make_float2(c[mi][ni][2] + b0, c[mi][ni][3] + b1);
        }
    }
}

__global__ __launch_bounds__(256, 1) void gemm1_kernel(
    const int* __restrict__ nodes, const float* __restrict__ feat)
{
    gemm_body(feat, nodes, BATCHN, g_Mh, g_Ml, g_d, g_U);
}

__global__ __launch_bounds__(256, 1) void gemm2_kernel(
    const float* __restrict__ bv, float* __restrict__ out)
{
    gemm_body(g_Z, nullptr, BATCHN, g_Wvh, g_Wvl, bv, out);
}

// ---------------------------------------------------------------------------
// Attention: one block per batch. scores_s = u . x_s, softmax, z = sum attn x_s
// ---------------------------------------------------------------------------
__global__ __launch_bounds__(256) void attn_kernel(
    const int* __restrict__ neigh, const float* __restrict__ feat)
{
    __shared__ float su[FEAT];
    __shared__ float snb[NSAMP][FEAT];
    __shared__ float ssc[NSAMP];
    const int tid = threadIdx.x, lane = tid & 31, warp = tid >> 5;
    const int b = blockIdx.x;

    su[tid] = g_U[(size_t)b * FEAT + tid];
    #pragma unroll
    for (int it = 0; it < 8; it++) {                 // 32 rows x 64 float4
        int i = tid + it * 256;
        int s = i >> 6, v = i & 63;
        int nb = neigh[(size_t)b * NSAMP + s];
        ((float4*)snb[s])[v] = ((const float4*)(feat + (size_t)nb * FEAT))[v];
    }
    __syncthreads();

    #pragma unroll
    for (int si = 0; si < 4; si++) {
        int s = warp * 4 + si;
        float dot = 0.f;
        #pragma unroll
        for (int k = 0; k < FEAT / 32; k++)
            dot += snb[s][lane + 32 * k] * su[lane + 32 * k];
        #pragma unroll
        for (int o = 16; o; o >>= 1) dot += __shfl_xor_sync(0xFFFFFFFFu, dot, o);
        if (lane == 0) ssc[s] = dot;
    }
    __syncthreads();

    if (warp == 0) {
        float v = ssc[lane];
        float mx = v;
        #pragma unroll
        for (int o = 16; o; o >>= 1) mx = fmaxf(mx, __shfl_xor_sync(0xFFFFFFFFu, mx, o));
        float e = expf(v - mx);
        float sm = e;
        #pragma unroll
        for (int o = 16; o; o >>= 1) sm += __shfl_xor_sync(0xFFFFFFFFu, sm, o);
        ssc[lane] = e / sm;
    }
    __syncthreads();

    float z = 0.f;
    #pragma unroll
    for (int s = 0; s < NSAMP; s++) z += ssc[s] * snb[s][tid];
    g_Z[(size_t)b * FEAT + tid] = z;
}

// ---------------------------------------------------------------------------
// Launch
// ---------------------------------------------------------------------------
extern "C" void kernel_launch(void* const* d_in, const int* in_sizes, int n_in,
                              void* d_out, int out_size)
{
    const int*   nodes = (const int*)  d_in[0];
    const int*   neigh = (const int*)  d_in[1];
    const float* feat  = (const float*)d_in[2];
    const float* Wq    = (const float*)d_in[3];
    const float* bq    = (const float*)d_in[4];
    const float* Wk    = (const float*)d_in[5];
    // bk (d_in[6]) drops out of softmax (constant shift over s) — unused.
    const float* Wv    = (const float*)d_in[7];
    const float* bv    = (const float*)d_in[8];
    float* out = (float*)d_out;

    cudaFuncSetAttribute(gemm1_kernel, cudaFuncAttributeMaxDynamicSharedMemorySize, SMEM_GEMM);
    cudaFuncSetAttribute(gemm2_kernel, cudaFuncAttributeMaxDynamicSharedMemorySize, SMEM_GEMM);

    precompute_M_kernel<<<dim3(16, 16), 256>>>(Wq, Wk);
    precompute_d_kernel<<<32, 256>>>(Wk, bq);
    prep_wv_kernel<<<256, 256>>>(Wv);

    dim3 gg((BATCHN + 127) / 128, EMB / 128);       // (79, 2)
    gemm1_kernel<<<gg, 256, SMEM_GEMM>>>(nodes, feat);
    attn_kernel<<<BATCHN, 256>>>(neigh, feat);
    gemm2_kernel<<<gg, 256, SMEM_GEMM>>>(bv, out);
}